// round 4
// baseline (speedup 1.0000x reference)
#include <cuda_runtime.h>

// out[i] = cos(x[i,0] + w0), x: [N,2] float32 interleaved, N = 16777216 (2^24).
// Memory-bound streaming map: read 128MB (x), write 64MB (out).
// R4: isolate the MLP variable. 8 samples/thread with 4x plain __ldg float4 loads
// (MLP=4, L1-allocating — avoids the .cs sector-split pathology seen in R2),
// 2x streaming float4 stores, exact grid (8192 blocks x 256).

__global__ void __launch_bounds__(256)
hybrid_qnn_cos_kernel(const float4* __restrict__ x4,   // N/2 float4s (each = 2 samples)
                      const float* __restrict__ w,
                      float4* __restrict__ out4,       // N/4 float4s
                      int n_thread)                     // N/8 threads
{
    int t = blockIdx.x * blockDim.x + threadIdx.x;
    if (t >= n_thread) return;

    const float w0 = __ldg(w);

    // Front-batch 4 independent 128B loads (MLP=4).
    const float4* p = x4 + (size_t)t * 4;
    float4 a = __ldg(p + 0);
    float4 b = __ldg(p + 1);
    float4 c = __ldg(p + 2);
    float4 d = __ldg(p + 3);

    float4 o0, o1;
    o0.x = cosf(a.x + w0);
    o0.y = cosf(a.z + w0);
    o0.z = cosf(b.x + w0);
    o0.w = cosf(b.z + w0);
    o1.x = cosf(c.x + w0);
    o1.y = cosf(c.z + w0);
    o1.z = cosf(d.x + w0);
    o1.w = cosf(d.z + w0);

    float4* q = out4 + (size_t)t * 2;
    __stcs(q + 0, o0);
    __stcs(q + 1, o1);
}

extern "C" void kernel_launch(void* const* d_in, const int* in_sizes, int n_in,
                              void* d_out, int out_size)
{
    const float4* x4 = (const float4*)d_in[0];   // x: [N,2] float32
    const float*  w  = (const float*)d_in[1];    // weights: [2] float32
    float4* out4 = (float4*)d_out;

    int n = in_sizes[0] / 2;        // N samples
    int n_thread = n / 8;           // 8 samples per thread (N = 2^24, divisible)

    const int threads = 256;
    int blocks = (n_thread + threads - 1) / threads;   // 8192 blocks

    hybrid_qnn_cos_kernel<<<blocks, threads>>>(x4, w, out4, n_thread);
}

// round 5
// speedup vs baseline: 1.2114x; 1.2114x over previous
#include <cuda_runtime.h>

// out[i] = cos(x[i,0] + w0), x: [N,2] float32 interleaved, N = 16777216 (2^24).
// Memory-bound streaming map: read 128MB (x), write 64MB (out).
// R5: warp-contiguous MLP=4. Each warp owns 128 consecutive float4s of x;
// each thread does 4 loads at lane+32k (every LDG.128 is a perfectly coalesced
// 512B / 4-line wavefront group) and 4 coalesced float2 stores.

__global__ void __launch_bounds__(256)
hybrid_qnn_cos_kernel(const float4* __restrict__ x4,   // N/2 float4s (each = 2 samples)
                      const float* __restrict__ w,
                      float2* __restrict__ out2,       // N/2 float2s
                      int n_x4)                         // N/2
{
    const float w0 = __ldg(w);

    int t = blockIdx.x * blockDim.x + threadIdx.x;
    int warp = t >> 5;
    int lane = t & 31;
    size_t base = (size_t)warp * 128 + lane;
    if (base + 96 >= (size_t)n_x4 + 96) return;  // exact grid; cheap guard

    // 4 independent, warp-coalesced 128B loads (MLP=4, 4 lines per instruction).
    float4 a = __ldg(x4 + base);
    float4 b = __ldg(x4 + base + 32);
    float4 c = __ldg(x4 + base + 64);
    float4 d = __ldg(x4 + base + 96);

    float2 oa = make_float2(cosf(a.x + w0), cosf(a.z + w0));
    float2 ob = make_float2(cosf(b.x + w0), cosf(b.z + w0));
    float2 oc = make_float2(cosf(c.x + w0), cosf(c.z + w0));
    float2 od = make_float2(cosf(d.x + w0), cosf(d.z + w0));

    // 4 warp-coalesced 8B stores (256B per instruction), streaming hint.
    __stcs(out2 + base, oa);
    __stcs(out2 + base + 32, ob);
    __stcs(out2 + base + 64, oc);
    __stcs(out2 + base + 96, od);
}

extern "C" void kernel_launch(void* const* d_in, const int* in_sizes, int n_in,
                              void* d_out, int out_size)
{
    const float4* x4 = (const float4*)d_in[0];   // x: [N,2] float32
    const float*  w  = (const float*)d_in[1];    // weights: [2] float32
    float2* out2 = (float2*)d_out;

    int n = in_sizes[0] / 2;        // N samples
    int n_x4 = n / 2;               // number of float4s in x (2^23)
    int n_thread = n_x4 / 4;        // 4 float4s (8 samples) per thread (2^21)

    const int threads = 256;
    int blocks = (n_thread + threads - 1) / threads;   // 8192 blocks

    hybrid_qnn_cos_kernel<<<blocks, threads>>>(x4, w, out2, n_x4);
}